// round 1
// baseline (speedup 1.0000x reference)
#include <cuda_runtime.h>
#include <cuda_bf16.h>
#include <cstdint>

#define N_NODES 100000
#define N_EDGES 1600000
#define D 128

// Scratch (device globals: allocation-free, module-load-time storage)
__device__ float g_h[(size_t)N_NODES * D];   // 51.2 MB: h = (xW + b) * rsqrt(deg_s)
__device__ int   g_deg_s[N_NODES];
__device__ int   g_deg_r[N_NODES];

// ---------------------------------------------------------------------------
// K0: zero degree arrays + output
// ---------------------------------------------------------------------------
__global__ void zero_kernel(float4* __restrict__ out)
{
    const int stride = gridDim.x * blockDim.x;
    int i = blockIdx.x * blockDim.x + threadIdx.x;
    const int n4 = N_NODES * D / 4;
    for (int j = i; j < n4; j += stride)
        out[j] = make_float4(0.f, 0.f, 0.f, 0.f);
    for (int j = i; j < N_NODES; j += stride) {
        g_deg_s[j] = 0;
        g_deg_r[j] = 0;
    }
}

// ---------------------------------------------------------------------------
// K1: degree histogram (int REDG)
// ---------------------------------------------------------------------------
__global__ void degree_kernel(const int* __restrict__ s, const int* __restrict__ r)
{
    int i = blockIdx.x * blockDim.x + threadIdx.x;
    if (i < N_EDGES) {
        atomicAdd(&g_deg_s[s[i]], 1);
        atomicAdd(&g_deg_r[r[i]], 1);
    }
}

// ---------------------------------------------------------------------------
// K2: SGEMM h = (x @ W + bias) * rsqrt(max(deg_s,1))
// Block: 256 threads, tile 64 rows x 128 cols, per-thread 8x4 microtile.
// ---------------------------------------------------------------------------
#define BM 64
#define BK 16

__global__ __launch_bounds__(256, 2)
void gemm_kernel(const float* __restrict__ x,
                 const float* __restrict__ w,
                 const float* __restrict__ bias)
{
    __shared__ float As[BK][BM + 8];   // A transposed, padded (stride 72 floats, 16B-aligned rows)
    __shared__ float Bs[BK][D];        // 16 x 128

    const int tid = threadIdx.x;
    const int tx  = tid & 31;          // column group: cols tx*4 .. tx*4+3
    const int ty  = tid >> 5;          // row group (warp id): rows ty*8 .. ty*8+7
    const int row0 = blockIdx.x * BM;

    // A-load mapping: one float4 per thread (64 rows x 4 float4s = 256)
    const int a_row = tid >> 2;        // 0..63
    const int a_col = (tid & 3) * 4;   // 0,4,8,12

    float acc[8][4];
#pragma unroll
    for (int m = 0; m < 8; m++)
#pragma unroll
        for (int n = 0; n < 4; n++) acc[m][n] = 0.f;

    for (int k0 = 0; k0 < D; k0 += BK) {
        // Load A tile (transposed into smem)
        {
            const int gr = row0 + a_row;
            float4 av = make_float4(0.f, 0.f, 0.f, 0.f);
            if (gr < N_NODES)
                av = *reinterpret_cast<const float4*>(&x[(size_t)gr * D + k0 + a_col]);
            As[a_col + 0][a_row] = av.x;
            As[a_col + 1][a_row] = av.y;
            As[a_col + 2][a_row] = av.z;
            As[a_col + 3][a_row] = av.w;
        }
        // Load B tile: 16x128 = 512 float4s, 2 per thread
#pragma unroll
        for (int p = 0; p < 2; p++) {
            const int idx = tid + p * 256;
            const int br = idx >> 5;
            const int bc = (idx & 31) * 4;
            *reinterpret_cast<float4*>(&Bs[br][bc]) =
                *reinterpret_cast<const float4*>(&w[(size_t)(k0 + br) * D + bc]);
        }
        __syncthreads();

#pragma unroll
        for (int kk = 0; kk < BK; kk++) {
            float4 a0 = *reinterpret_cast<const float4*>(&As[kk][ty * 8 + 0]);
            float4 a1 = *reinterpret_cast<const float4*>(&As[kk][ty * 8 + 4]);
            float4 b  = *reinterpret_cast<const float4*>(&Bs[kk][tx * 4]);
            const float a[8] = {a0.x, a0.y, a0.z, a0.w, a1.x, a1.y, a1.z, a1.w};
            const float bb[4] = {b.x, b.y, b.z, b.w};
#pragma unroll
            for (int m = 0; m < 8; m++)
#pragma unroll
                for (int n = 0; n < 4; n++)
                    acc[m][n] = fmaf(a[m], bb[n], acc[m][n]);
        }
        __syncthreads();
    }

    const float4 bv = *reinterpret_cast<const float4*>(&bias[tx * 4]);
#pragma unroll
    for (int m = 0; m < 8; m++) {
        const int gr = row0 + ty * 8 + m;
        if (gr < N_NODES) {
            const float sc = rsqrtf(fmaxf((float)g_deg_s[gr], 1.0f));
            float4 v;
            v.x = (acc[m][0] + bv.x) * sc;
            v.y = (acc[m][1] + bv.y) * sc;
            v.z = (acc[m][2] + bv.z) * sc;
            v.w = (acc[m][3] + bv.w) * sc;
            *reinterpret_cast<float4*>(&g_h[(size_t)gr * D + tx * 4]) = v;
        }
    }
}

// ---------------------------------------------------------------------------
// K3: edge scatter-sum. One warp per edge; each lane handles one float4
// (4 features). red.global.add.v4.f32 = no-return vectorized reduction.
// ---------------------------------------------------------------------------
__global__ __launch_bounds__(256)
void scatter_kernel(const int* __restrict__ s, const int* __restrict__ r,
                    float* __restrict__ out)
{
    const int warp = (blockIdx.x * blockDim.x + threadIdx.x) >> 5;
    const int lane = threadIdx.x & 31;
    if (warp >= N_EDGES) return;
    const int ss = __ldg(&s[warp]);
    const int rr = __ldg(&r[warp]);
    const float4 v = *reinterpret_cast<const float4*>(&g_h[(size_t)ss * D + lane * 4]);
    float* dst = &out[(size_t)rr * D + lane * 4];
    asm volatile("red.global.add.v4.f32 [%0], {%1, %2, %3, %4};"
                 :: "l"(dst), "f"(v.x), "f"(v.y), "f"(v.z), "f"(v.w)
                 : "memory");
}

// ---------------------------------------------------------------------------
// K4: post-scale out by rsqrt(max(deg_r,1))
// ---------------------------------------------------------------------------
__global__ void scale_kernel(float4* __restrict__ out)
{
    const int i = blockIdx.x * blockDim.x + threadIdx.x;  // one float4 each
    const int n4 = N_NODES * D / 4;
    if (i < n4) {
        const int node = i >> 5;   // 32 float4 per node row
        const float sc = rsqrtf(fmaxf((float)g_deg_r[node], 1.0f));
        float4 v = out[i];
        v.x *= sc; v.y *= sc; v.z *= sc; v.w *= sc;
        out[i] = v;
    }
}

// ---------------------------------------------------------------------------
// Inputs (metadata order): x, senders, receivers, n_node, weight, bias
// ---------------------------------------------------------------------------
extern "C" void kernel_launch(void* const* d_in, const int* in_sizes, int n_in,
                              void* d_out, int out_size)
{
    const float* x       = (const float*)d_in[0];
    const int*   senders = (const int*)d_in[1];
    const int*   recvs   = (const int*)d_in[2];
    const float* weight  = (const float*)d_in[4];
    const float* bias    = (const float*)d_in[5];
    float* out = (float*)d_out;

    // K0: zero
    zero_kernel<<<1024, 256>>>((float4*)out);

    // K1: degrees
    degree_kernel<<<(N_EDGES + 255) / 256, 256>>>(senders, recvs);

    // K2: GEMM + prescale
    gemm_kernel<<<(N_NODES + BM - 1) / BM, 256>>>(x, weight, bias);

    // K3: scatter (1 warp per edge, 8 warps per block)
    scatter_kernel<<<N_EDGES / 8, 256>>>(senders, recvs, out);

    // K4: post-scale
    scale_kernel<<<(N_NODES * D / 4 + 255) / 256, 256>>>((float4*)out);
}

// round 2
// speedup vs baseline: 1.7389x; 1.7389x over previous
#include <cuda_runtime.h>
#include <cuda_bf16.h>
#include <cstdint>

#define N_NODES 100000
#define N_EDGES 1600000
#define D 128

#define SCAN_B 512
#define NUM_SCAN_BLOCKS ((N_NODES + SCAN_B - 1) / SCAN_B)   // 196

// Scratch (device globals: allocation-free)
__device__ float g_h[(size_t)N_NODES * D];   // 51.2 MB: h = (xW + b) * rsqrt(deg_s)
__device__ int   g_deg_s[N_NODES];
__device__ int   g_deg_r[N_NODES];
__device__ int   g_off[N_NODES];             // exclusive CSR row offsets (by receiver)
__device__ int   g_cursor[N_NODES];          // fill cursors
__device__ int   g_bsum[NUM_SCAN_BLOCKS];    // per-block scan totals
__device__ int   g_boff[NUM_SCAN_BLOCKS];    // exclusive block offsets
__device__ int   g_csr[N_EDGES];             // sender ids bucketed by receiver

// ---------------------------------------------------------------------------
// K0: zero degree arrays + cursors (output no longer needs zeroing)
// ---------------------------------------------------------------------------
__global__ void zero_kernel()
{
    const int stride = gridDim.x * blockDim.x;
    for (int j = blockIdx.x * blockDim.x + threadIdx.x; j < N_NODES; j += stride) {
        g_deg_s[j] = 0;
        g_deg_r[j] = 0;
        g_cursor[j] = 0;
    }
}

// ---------------------------------------------------------------------------
// K1: degree histogram (int REDG)
// ---------------------------------------------------------------------------
__global__ void degree_kernel(const int* __restrict__ s, const int* __restrict__ r)
{
    int i = blockIdx.x * blockDim.x + threadIdx.x;
    if (i < N_EDGES) {
        atomicAdd(&g_deg_s[s[i]], 1);
        atomicAdd(&g_deg_r[r[i]], 1);
    }
}

// ---------------------------------------------------------------------------
// K2a/b/c: exclusive prefix scan of g_deg_r -> g_off  (3-kernel scan)
// ---------------------------------------------------------------------------
__global__ void scan_part_kernel()
{
    __shared__ int sh[SCAN_B];
    const int t = threadIdx.x;
    const int idx = blockIdx.x * SCAN_B + t;
    const int v = (idx < N_NODES) ? g_deg_r[idx] : 0;
    sh[t] = v;
    __syncthreads();
#pragma unroll
    for (int o = 1; o < SCAN_B; o <<= 1) {
        int x = (t >= o) ? sh[t - o] : 0;
        __syncthreads();
        sh[t] += x;
        __syncthreads();
    }
    if (idx < N_NODES) g_off[idx] = sh[t] - v;     // exclusive within block
    if (t == SCAN_B - 1) g_bsum[blockIdx.x] = sh[t];
}

__global__ void scan_top_kernel()
{
    __shared__ int sh[256];
    const int t = threadIdx.x;    // single block, 256 >= NUM_SCAN_BLOCKS
    const int v = (t < NUM_SCAN_BLOCKS) ? g_bsum[t] : 0;
    sh[t] = v;
    __syncthreads();
#pragma unroll
    for (int o = 1; o < 256; o <<= 1) {
        int x = (t >= o) ? sh[t - o] : 0;
        __syncthreads();
        sh[t] += x;
        __syncthreads();
    }
    if (t < NUM_SCAN_BLOCKS) g_boff[t] = sh[t] - v;
}

__global__ void scan_add_kernel()
{
    const int idx = blockIdx.x * blockDim.x + threadIdx.x;
    if (idx < N_NODES) g_off[idx] += g_boff[idx / SCAN_B];
}

// ---------------------------------------------------------------------------
// K3: CSR fill — bucket sender ids by receiver
// ---------------------------------------------------------------------------
__global__ void fill_kernel(const int* __restrict__ s, const int* __restrict__ r)
{
    const int i = blockIdx.x * blockDim.x + threadIdx.x;
    if (i < N_EDGES) {
        const int rr = r[i];
        const int pos = atomicAdd(&g_cursor[rr], 1);
        g_csr[g_off[rr] + pos] = s[i];
    }
}

// ---------------------------------------------------------------------------
// K4: SGEMM h = (x @ W + bias) * rsqrt(max(deg_s,1))
// ---------------------------------------------------------------------------
#define BM 64
#define BK 16

__global__ __launch_bounds__(256, 2)
void gemm_kernel(const float* __restrict__ x,
                 const float* __restrict__ w,
                 const float* __restrict__ bias)
{
    __shared__ float As[BK][BM + 8];
    __shared__ float Bs[BK][D];

    const int tid = threadIdx.x;
    const int tx  = tid & 31;
    const int ty  = tid >> 5;
    const int row0 = blockIdx.x * BM;

    const int a_row = tid >> 2;
    const int a_col = (tid & 3) * 4;

    float acc[8][4];
#pragma unroll
    for (int m = 0; m < 8; m++)
#pragma unroll
        for (int n = 0; n < 4; n++) acc[m][n] = 0.f;

    for (int k0 = 0; k0 < D; k0 += BK) {
        {
            const int gr = row0 + a_row;
            float4 av = make_float4(0.f, 0.f, 0.f, 0.f);
            if (gr < N_NODES)
                av = *reinterpret_cast<const float4*>(&x[(size_t)gr * D + k0 + a_col]);
            As[a_col + 0][a_row] = av.x;
            As[a_col + 1][a_row] = av.y;
            As[a_col + 2][a_row] = av.z;
            As[a_col + 3][a_row] = av.w;
        }
#pragma unroll
        for (int p = 0; p < 2; p++) {
            const int idx = tid + p * 256;
            const int br = idx >> 5;
            const int bc = (idx & 31) * 4;
            *reinterpret_cast<float4*>(&Bs[br][bc]) =
                *reinterpret_cast<const float4*>(&w[(size_t)(k0 + br) * D + bc]);
        }
        __syncthreads();

#pragma unroll
        for (int kk = 0; kk < BK; kk++) {
            float4 a0 = *reinterpret_cast<const float4*>(&As[kk][ty * 8 + 0]);
            float4 a1 = *reinterpret_cast<const float4*>(&As[kk][ty * 8 + 4]);
            float4 b  = *reinterpret_cast<const float4*>(&Bs[kk][tx * 4]);
            const float a[8] = {a0.x, a0.y, a0.z, a0.w, a1.x, a1.y, a1.z, a1.w};
            const float bb[4] = {b.x, b.y, b.z, b.w};
#pragma unroll
            for (int m = 0; m < 8; m++)
#pragma unroll
                for (int n = 0; n < 4; n++)
                    acc[m][n] = fmaf(a[m], bb[n], acc[m][n]);
        }
        __syncthreads();
    }

    const float4 bv = *reinterpret_cast<const float4*>(&bias[tx * 4]);
#pragma unroll
    for (int m = 0; m < 8; m++) {
        const int gr = row0 + ty * 8 + m;
        if (gr < N_NODES) {
            const float sc = rsqrtf(fmaxf((float)g_deg_s[gr], 1.0f));
            float4 v;
            v.x = (acc[m][0] + bv.x) * sc;
            v.y = (acc[m][1] + bv.y) * sc;
            v.z = (acc[m][2] + bv.z) * sc;
            v.w = (acc[m][3] + bv.w) * sc;
            *reinterpret_cast<float4*>(&g_h[(size_t)gr * D + tx * 4]) = v;
        }
    }
}

// ---------------------------------------------------------------------------
// K5: gather-aggregate. One warp per node: walk incoming sender list,
// accumulate h rows in registers (float4 per lane), fused rsqrt(deg_r)
// epilogue, single store. No f32 atomics anywhere.
// ---------------------------------------------------------------------------
__global__ __launch_bounds__(256)
void gather_kernel(float* __restrict__ out)
{
    const int node = (blockIdx.x * blockDim.x + threadIdx.x) >> 5;
    const int lane = threadIdx.x & 31;
    if (node >= N_NODES) return;

    const int deg = g_deg_r[node];
    const int beg = g_off[node];
    const int end = beg + deg;

    float4 acc = make_float4(0.f, 0.f, 0.f, 0.f);
    const int fo = lane * 4;

    int j = beg;
    // 4-deep unroll: batch the index loads and the 4 row loads for MLP
    for (; j + 4 <= end; j += 4) {
        const int s0 = g_csr[j + 0];
        const int s1 = g_csr[j + 1];
        const int s2 = g_csr[j + 2];
        const int s3 = g_csr[j + 3];
        const float4 v0 = *reinterpret_cast<const float4*>(&g_h[(size_t)s0 * D + fo]);
        const float4 v1 = *reinterpret_cast<const float4*>(&g_h[(size_t)s1 * D + fo]);
        const float4 v2 = *reinterpret_cast<const float4*>(&g_h[(size_t)s2 * D + fo]);
        const float4 v3 = *reinterpret_cast<const float4*>(&g_h[(size_t)s3 * D + fo]);
        acc.x += (v0.x + v1.x) + (v2.x + v3.x);
        acc.y += (v0.y + v1.y) + (v2.y + v3.y);
        acc.z += (v0.z + v1.z) + (v2.z + v3.z);
        acc.w += (v0.w + v1.w) + (v2.w + v3.w);
    }
    for (; j < end; j++) {
        const int ss = g_csr[j];
        const float4 v = *reinterpret_cast<const float4*>(&g_h[(size_t)ss * D + fo]);
        acc.x += v.x; acc.y += v.y; acc.z += v.z; acc.w += v.w;
    }

    const float sc = rsqrtf(fmaxf((float)deg, 1.0f));
    acc.x *= sc; acc.y *= sc; acc.z *= sc; acc.w *= sc;
    *reinterpret_cast<float4*>(&out[(size_t)node * D + fo]) = acc;
}

// ---------------------------------------------------------------------------
// Inputs (metadata order): x, senders, receivers, n_node, weight, bias
// ---------------------------------------------------------------------------
extern "C" void kernel_launch(void* const* d_in, const int* in_sizes, int n_in,
                              void* d_out, int out_size)
{
    const float* x       = (const float*)d_in[0];
    const int*   senders = (const int*)d_in[1];
    const int*   recvs   = (const int*)d_in[2];
    const float* weight  = (const float*)d_in[4];
    const float* bias    = (const float*)d_in[5];
    float* out = (float*)d_out;

    zero_kernel<<<256, 256>>>();
    degree_kernel<<<(N_EDGES + 255) / 256, 256>>>(senders, recvs);

    scan_part_kernel<<<NUM_SCAN_BLOCKS, SCAN_B>>>();
    scan_top_kernel<<<1, 256>>>();
    scan_add_kernel<<<(N_NODES + 255) / 256, 256>>>();

    fill_kernel<<<(N_EDGES + 255) / 256, 256>>>(senders, recvs);

    gemm_kernel<<<(N_NODES + BM - 1) / BM, 256>>>(x, weight, bias);

    gather_kernel<<<(N_NODES * 32 + 255) / 256, 256>>>(out);
}

// round 3
// speedup vs baseline: 2.2141x; 1.2733x over previous
#include <cuda_runtime.h>
#include <cuda_bf16.h>
#include <cstdint>

#define N_NODES 100000
#define N_EDGES 1600000
#define D 128

#define SCAN_B 512
#define NUM_SCAN_BLOCKS ((N_NODES + SCAN_B - 1) / SCAN_B)   // 196

// Scratch (device globals: allocation-free)
__device__ float g_h[(size_t)N_NODES * D];   // 51.2 MB
__device__ int   g_deg_s[N_NODES];
__device__ int   g_deg_r[N_NODES];
__device__ int   g_off[N_NODES];
__device__ int   g_cursor[N_NODES];
__device__ int   g_bsum[NUM_SCAN_BLOCKS];
__device__ int   g_boff[NUM_SCAN_BLOCKS];
__device__ int   g_csr[N_EDGES];

// ---------------------------------------------------------------------------
__global__ void zero_kernel()
{
    const int stride = gridDim.x * blockDim.x;
    for (int j = blockIdx.x * blockDim.x + threadIdx.x; j < N_NODES; j += stride) {
        g_deg_s[j] = 0;
        g_deg_r[j] = 0;
        g_cursor[j] = 0;
    }
}

__global__ void degree_kernel(const int* __restrict__ s, const int* __restrict__ r)
{
    int i = blockIdx.x * blockDim.x + threadIdx.x;
    if (i < N_EDGES) {
        atomicAdd(&g_deg_s[s[i]], 1);
        atomicAdd(&g_deg_r[r[i]], 1);
    }
}

// ---------------------------------------------------------------------------
__global__ void scan_part_kernel()
{
    __shared__ int sh[SCAN_B];
    const int t = threadIdx.x;
    const int idx = blockIdx.x * SCAN_B + t;
    const int v = (idx < N_NODES) ? g_deg_r[idx] : 0;
    sh[t] = v;
    __syncthreads();
#pragma unroll
    for (int o = 1; o < SCAN_B; o <<= 1) {
        int x = (t >= o) ? sh[t - o] : 0;
        __syncthreads();
        sh[t] += x;
        __syncthreads();
    }
    if (idx < N_NODES) g_off[idx] = sh[t] - v;
    if (t == SCAN_B - 1) g_bsum[blockIdx.x] = sh[t];
}

__global__ void scan_top_kernel()
{
    __shared__ int sh[256];
    const int t = threadIdx.x;
    const int v = (t < NUM_SCAN_BLOCKS) ? g_bsum[t] : 0;
    sh[t] = v;
    __syncthreads();
#pragma unroll
    for (int o = 1; o < 256; o <<= 1) {
        int x = (t >= o) ? sh[t - o] : 0;
        __syncthreads();
        sh[t] += x;
        __syncthreads();
    }
    if (t < NUM_SCAN_BLOCKS) g_boff[t] = sh[t] - v;
}

__global__ void scan_add_kernel()
{
    const int idx = blockIdx.x * blockDim.x + threadIdx.x;
    if (idx < N_NODES) g_off[idx] += g_boff[idx / SCAN_B];
}

__global__ void fill_kernel(const int* __restrict__ s, const int* __restrict__ r)
{
    const int i = blockIdx.x * blockDim.x + threadIdx.x;
    if (i < N_EDGES) {
        const int rr = r[i];
        const int pos = atomicAdd(&g_cursor[rr], 1);
        g_csr[g_off[rr] + pos] = s[i];
    }
}

// ---------------------------------------------------------------------------
// TF32 tensor-core GEMM: h = (x @ W + bias) * rsqrt(max(deg_s,1))
// Block tile 128x128, 8 warps (4x2), warp tile 32x64, BK=32.
// mma.sync.aligned.m16n8k8.row.col.f32.tf32.tf32.f32
// ---------------------------------------------------------------------------
#define GBM 128
#define GBK 32
#define A_STRIDE 36    // (4*gid + tig) mod 32 unique -> conflict-free A frag loads
#define B_STRIDE 136   // (8*tig + gid) mod 32 unique -> conflict-free B frag loads

__device__ __forceinline__ uint32_t f2tf32(float f)
{
    uint32_t r;
    asm("cvt.rna.tf32.f32 %0, %1;" : "=r"(r) : "f"(f));
    return r;
}

__device__ __forceinline__ void mma_tf32(float4& d,
                                         uint32_t a0, uint32_t a1, uint32_t a2, uint32_t a3,
                                         uint32_t b0, uint32_t b1)
{
    asm volatile(
        "mma.sync.aligned.m16n8k8.row.col.f32.tf32.tf32.f32 "
        "{%0,%1,%2,%3}, {%4,%5,%6,%7}, {%8,%9}, {%0,%1,%2,%3};"
        : "+f"(d.x), "+f"(d.y), "+f"(d.z), "+f"(d.w)
        : "r"(a0), "r"(a1), "r"(a2), "r"(a3), "r"(b0), "r"(b1));
}

__global__ __launch_bounds__(256, 2)
void gemm_tc_kernel(const float* __restrict__ x,
                    const float* __restrict__ w,
                    const float* __restrict__ bias)
{
    __shared__ uint32_t As[GBM][A_STRIDE];   // 18.4 KB
    __shared__ uint32_t Bs[GBK][B_STRIDE];   // 17.4 KB

    const int tid  = threadIdx.x;
    const int warp = tid >> 5;
    const int lane = tid & 31;
    const int gid  = lane >> 2;      // 0..7
    const int tig  = lane & 3;       // 0..3
    const int wm   = warp >> 1;      // 0..3 -> m offset wm*32
    const int wn   = warp & 1;       // 0..1 -> n offset wn*64
    const int row0 = blockIdx.x * GBM;

    float4 acc[2][8];
#pragma unroll
    for (int mt = 0; mt < 2; mt++)
#pragma unroll
        for (int nt = 0; nt < 8; nt++)
            acc[mt][nt] = make_float4(0.f, 0.f, 0.f, 0.f);

    for (int kb = 0; kb < D; kb += GBK) {
        // Load A tile (128 x 32): 1024 float4s, 4 per thread; convert to tf32.
#pragma unroll
        for (int p = 0; p < 4; p++) {
            const int idx = tid + p * 256;
            const int r   = idx >> 3;          // 0..127
            const int c   = (idx & 7) * 4;     // 0..28
            const int gr  = row0 + r;
            float4 v = make_float4(0.f, 0.f, 0.f, 0.f);
            if (gr < N_NODES)
                v = *reinterpret_cast<const float4*>(&x[(size_t)gr * D + kb + c]);
            As[r][c + 0] = f2tf32(v.x);
            As[r][c + 1] = f2tf32(v.y);
            As[r][c + 2] = f2tf32(v.z);
            As[r][c + 3] = f2tf32(v.w);
        }
        // Load B tile (32 x 128): 1024 float4s, 4 per thread.
#pragma unroll
        for (int p = 0; p < 4; p++) {
            const int idx = tid + p * 256;
            const int r   = idx >> 5;          // 0..31
            const int c   = (idx & 31) * 4;    // 0..124
            const float4 v = *reinterpret_cast<const float4*>(&w[(size_t)(kb + r) * D + c]);
            Bs[r][c + 0] = f2tf32(v.x);
            Bs[r][c + 1] = f2tf32(v.y);
            Bs[r][c + 2] = f2tf32(v.z);
            Bs[r][c + 3] = f2tf32(v.w);
        }
        __syncthreads();

#pragma unroll
        for (int kc = 0; kc < GBK; kc += 8) {
            uint32_t a[2][4];
#pragma unroll
            for (int mt = 0; mt < 2; mt++) {
                const int r = wm * 32 + mt * 16;
                a[mt][0] = As[r + gid    ][kc + tig    ];
                a[mt][1] = As[r + gid + 8][kc + tig    ];
                a[mt][2] = As[r + gid    ][kc + tig + 4];
                a[mt][3] = As[r + gid + 8][kc + tig + 4];
            }
#pragma unroll
            for (int nt = 0; nt < 8; nt++) {
                const int n0 = wn * 64 + nt * 8;
                const uint32_t b0 = Bs[kc + tig    ][n0 + gid];
                const uint32_t b1 = Bs[kc + tig + 4][n0 + gid];
                mma_tf32(acc[0][nt], a[0][0], a[0][1], a[0][2], a[0][3], b0, b1);
                mma_tf32(acc[1][nt], a[1][0], a[1][1], a[1][2], a[1][3], b0, b1);
            }
        }
        __syncthreads();
    }

    // Epilogue: bias + rsqrt(deg_s) prescale, write g_h.
    float2 bv[8];
#pragma unroll
    for (int nt = 0; nt < 8; nt++) {
        const int n = wn * 64 + nt * 8 + tig * 2;
        bv[nt].x = __ldg(&bias[n]);
        bv[nt].y = __ldg(&bias[n + 1]);
    }
#pragma unroll
    for (int mt = 0; mt < 2; mt++) {
        const int rbase = row0 + wm * 32 + mt * 16;
        const int r0 = rbase + gid;
        const int r1 = rbase + gid + 8;
        const float s0 = (r0 < N_NODES) ? rsqrtf(fmaxf((float)g_deg_s[r0], 1.0f)) : 0.f;
        const float s1 = (r1 < N_NODES) ? rsqrtf(fmaxf((float)g_deg_s[r1], 1.0f)) : 0.f;
#pragma unroll
        for (int nt = 0; nt < 8; nt++) {
            const int n = wn * 64 + nt * 8 + tig * 2;
            if (r0 < N_NODES) {
                float2 o;
                o.x = (acc[mt][nt].x + bv[nt].x) * s0;
                o.y = (acc[mt][nt].y + bv[nt].y) * s0;
                *reinterpret_cast<float2*>(&g_h[(size_t)r0 * D + n]) = o;
            }
            if (r1 < N_NODES) {
                float2 o;
                o.x = (acc[mt][nt].z + bv[nt].x) * s1;
                o.y = (acc[mt][nt].w + bv[nt].y) * s1;
                *reinterpret_cast<float2*>(&g_h[(size_t)r1 * D + n]) = o;
            }
        }
    }
}

// ---------------------------------------------------------------------------
// Gather-aggregate (unchanged from R2 — known good)
// ---------------------------------------------------------------------------
__global__ __launch_bounds__(256)
void gather_kernel(float* __restrict__ out)
{
    const int node = (blockIdx.x * blockDim.x + threadIdx.x) >> 5;
    const int lane = threadIdx.x & 31;
    if (node >= N_NODES) return;

    const int deg = g_deg_r[node];
    const int beg = g_off[node];
    const int end = beg + deg;

    float4 acc = make_float4(0.f, 0.f, 0.f, 0.f);
    const int fo = lane * 4;

    int j = beg;
    for (; j + 4 <= end; j += 4) {
        const int s0 = g_csr[j + 0];
        const int s1 = g_csr[j + 1];
        const int s2 = g_csr[j + 2];
        const int s3 = g_csr[j + 3];
        const float4 v0 = *reinterpret_cast<const float4*>(&g_h[(size_t)s0 * D + fo]);
        const float4 v1 = *reinterpret_cast<const float4*>(&g_h[(size_t)s1 * D + fo]);
        const float4 v2 = *reinterpret_cast<const float4*>(&g_h[(size_t)s2 * D + fo]);
        const float4 v3 = *reinterpret_cast<const float4*>(&g_h[(size_t)s3 * D + fo]);
        acc.x += (v0.x + v1.x) + (v2.x + v3.x);
        acc.y += (v0.y + v1.y) + (v2.y + v3.y);
        acc.z += (v0.z + v1.z) + (v2.z + v3.z);
        acc.w += (v0.w + v1.w) + (v2.w + v3.w);
    }
    for (; j < end; j++) {
        const int ss = g_csr[j];
        const float4 v = *reinterpret_cast<const float4*>(&g_h[(size_t)ss * D + fo]);
        acc.x += v.x; acc.y += v.y; acc.z += v.z; acc.w += v.w;
    }

    const float sc = rsqrtf(fmaxf((float)deg, 1.0f));
    acc.x *= sc; acc.y *= sc; acc.z *= sc; acc.w *= sc;
    *reinterpret_cast<float4*>(&out[(size_t)node * D + fo]) = acc;
}

// ---------------------------------------------------------------------------
extern "C" void kernel_launch(void* const* d_in, const int* in_sizes, int n_in,
                              void* d_out, int out_size)
{
    const float* x       = (const float*)d_in[0];
    const int*   senders = (const int*)d_in[1];
    const int*   recvs   = (const int*)d_in[2];
    const float* weight  = (const float*)d_in[4];
    const float* bias    = (const float*)d_in[5];
    float* out = (float*)d_out;

    zero_kernel<<<256, 256>>>();
    degree_kernel<<<(N_EDGES + 255) / 256, 256>>>(senders, recvs);

    scan_part_kernel<<<NUM_SCAN_BLOCKS, SCAN_B>>>();
    scan_top_kernel<<<1, 256>>>();
    scan_add_kernel<<<(N_NODES + 255) / 256, 256>>>();

    fill_kernel<<<(N_EDGES + 255) / 256, 256>>>(senders, recvs);

    gemm_tc_kernel<<<(N_NODES + GBM - 1) / GBM, 256>>>(x, weight, bias);

    gather_kernel<<<(N_NODES * 32 + 255) / 256, 256>>>(out);
}

// round 7
// speedup vs baseline: 2.3876x; 1.0784x over previous
#include <cuda_runtime.h>
#include <cuda_fp16.h>
#include <cuda_bf16.h>
#include <cstdint>

#define N_NODES 100000
#define N_EDGES 1600000
#define D 128

#define SCAN_B 512
#define NUM_SCAN_BLOCKS ((N_NODES + SCAN_B - 1) / SCAN_B)   // 196

// Scratch (device globals: allocation-free)
__device__ __half g_h[(size_t)N_NODES * D];   // 25.6 MB, fp16 h
__device__ int    g_deg_s[N_NODES];
__device__ int    g_deg_r[N_NODES];
__device__ int    g_off[N_NODES];             // after fill: END offset per node
__device__ int    g_bsum[NUM_SCAN_BLOCKS];
__device__ int    g_csr[N_EDGES];

// ---------------------------------------------------------------------------
__global__ void zero_kernel()
{
    const int stride = gridDim.x * blockDim.x;
    for (int j = blockIdx.x * blockDim.x + threadIdx.x; j < N_NODES; j += stride) {
        g_deg_s[j] = 0;
        g_deg_r[j] = 0;
    }
}

__global__ void degree_kernel(const int* __restrict__ s, const int* __restrict__ r)
{
    int i = blockIdx.x * blockDim.x + threadIdx.x;
    if (i < N_EDGES) {
        atomicAdd(&g_deg_s[s[i]], 1);
        atomicAdd(&g_deg_r[r[i]], 1);
    }
}

// ---------------------------------------------------------------------------
// Scan: per-512-block exclusive scan + per-block totals
// ---------------------------------------------------------------------------
__global__ void scan_part_kernel()
{
    __shared__ int sh[SCAN_B];
    const int t = threadIdx.x;
    const int idx = blockIdx.x * SCAN_B + t;
    const int v = (idx < N_NODES) ? g_deg_r[idx] : 0;
    sh[t] = v;
    __syncthreads();
#pragma unroll
    for (int o = 1; o < SCAN_B; o <<= 1) {
        int x = (t >= o) ? sh[t - o] : 0;
        __syncthreads();
        sh[t] += x;
        __syncthreads();
    }
    if (idx < N_NODES) g_off[idx] = sh[t] - v;
    if (t == SCAN_B - 1) g_bsum[blockIdx.x] = sh[t];
}

// scan_add with integrated top-level prefix: each 256-thread block covers one
// half of a single 512-wide scan block sb = blockIdx.x/2; it computes
// prefix = sum(g_bsum[0..sb-1]) with one block reduce (sb <= 195 < 256).
__global__ void scan_add_kernel()
{
    __shared__ int red[32];
    const int t  = threadIdx.x;
    const int sb = blockIdx.x >> 1;

    int v = (t < sb) ? g_bsum[t] : 0;
#pragma unroll
    for (int o = 16; o > 0; o >>= 1) v += __shfl_down_sync(0xffffffffu, v, o);
    if ((t & 31) == 0) red[t >> 5] = v;
    __syncthreads();
    if (t < 32) {
        int w = (t < 8) ? red[t] : 0;
#pragma unroll
        for (int o = 4; o > 0; o >>= 1) w += __shfl_down_sync(0xffffffffu, w, o);
        if (t == 0) red[0] = w;
    }
    __syncthreads();
    const int prefix = red[0];

    const int idx = blockIdx.x * 256 + t;
    if (idx < N_NODES) g_off[idx] += prefix;
}

// ---------------------------------------------------------------------------
// CSR fill: bump g_off in place (afterwards g_off[r] == row END)
// ---------------------------------------------------------------------------
__global__ void fill_kernel(const int* __restrict__ s, const int* __restrict__ r)
{
    const int i = blockIdx.x * blockDim.x + threadIdx.x;
    if (i < N_EDGES) {
        const int pos = atomicAdd(&g_off[r[i]], 1);
        g_csr[pos] = s[i];
    }
}

// ---------------------------------------------------------------------------
// TF32 tensor-core GEMM: h = (x @ W + bias) * rsqrt(max(deg_s,1)), fp16 out
// ---------------------------------------------------------------------------
#define GBM 128
#define GBK 32
#define A_STRIDE 36
#define B_STRIDE 136

__device__ __forceinline__ uint32_t f2tf32(float f)
{
    uint32_t r;
    asm("cvt.rna.tf32.f32 %0, %1;" : "=r"(r) : "f"(f));
    return r;
}

__device__ __forceinline__ void mma_tf32(float4& d,
                                         uint32_t a0, uint32_t a1, uint32_t a2, uint32_t a3,
                                         uint32_t b0, uint32_t b1)
{
    asm volatile(
        "mma.sync.aligned.m16n8k8.row.col.f32.tf32.tf32.f32 "
        "{%0,%1,%2,%3}, {%4,%5,%6,%7}, {%8,%9}, {%0,%1,%2,%3};"
        : "+f"(d.x), "+f"(d.y), "+f"(d.z), "+f"(d.w)
        : "r"(a0), "r"(a1), "r"(a2), "r"(a3), "r"(b0), "r"(b1));
}

__global__ __launch_bounds__(256, 2)
void gemm_tc_kernel(const float* __restrict__ x,
                    const float* __restrict__ w,
                    const float* __restrict__ bias)
{
    __shared__ uint32_t As[GBM][A_STRIDE];
    __shared__ uint32_t Bs[GBK][B_STRIDE];

    const int tid  = threadIdx.x;
    const int warp = tid >> 5;
    const int lane = tid & 31;
    const int gid  = lane >> 2;
    const int tig  = lane & 3;
    const int wm   = warp >> 1;
    const int wn   = warp & 1;
    const int row0 = blockIdx.x * GBM;

    float4 acc[2][8];
#pragma unroll
    for (int mt = 0; mt < 2; mt++)
#pragma unroll
        for (int nt = 0; nt < 8; nt++)
            acc[mt][nt] = make_float4(0.f, 0.f, 0.f, 0.f);

    for (int kb = 0; kb < D; kb += GBK) {
#pragma unroll
        for (int p = 0; p < 4; p++) {
            const int idx = tid + p * 256;
            const int r   = idx >> 3;
            const int c   = (idx & 7) * 4;
            const int gr  = row0 + r;
            float4 v = make_float4(0.f, 0.f, 0.f, 0.f);
            if (gr < N_NODES)
                v = *reinterpret_cast<const float4*>(&x[(size_t)gr * D + kb + c]);
            As[r][c + 0] = f2tf32(v.x);
            As[r][c + 1] = f2tf32(v.y);
            As[r][c + 2] = f2tf32(v.z);
            As[r][c + 3] = f2tf32(v.w);
        }
#pragma unroll
        for (int p = 0; p < 4; p++) {
            const int idx = tid + p * 256;
            const int r   = idx >> 5;
            const int c   = (idx & 31) * 4;
            const float4 v = *reinterpret_cast<const float4*>(&w[(size_t)(kb + r) * D + c]);
            Bs[r][c + 0] = f2tf32(v.x);
            Bs[r][c + 1] = f2tf32(v.y);
            Bs[r][c + 2] = f2tf32(v.z);
            Bs[r][c + 3] = f2tf32(v.w);
        }
        __syncthreads();

#pragma unroll
        for (int kc = 0; kc < GBK; kc += 8) {
            uint32_t a[2][4];
#pragma unroll
            for (int mt = 0; mt < 2; mt++) {
                const int r = wm * 32 + mt * 16;
                a[mt][0] = As[r + gid    ][kc + tig    ];
                a[mt][1] = As[r + gid + 8][kc + tig    ];
                a[mt][2] = As[r + gid    ][kc + tig + 4];
                a[mt][3] = As[r + gid + 8][kc + tig + 4];
            }
#pragma unroll
            for (int nt = 0; nt < 8; nt++) {
                const int n0 = wn * 64 + nt * 8;
                const uint32_t b0 = Bs[kc + tig    ][n0 + gid];
                const uint32_t b1 = Bs[kc + tig + 4][n0 + gid];
                mma_tf32(acc[0][nt], a[0][0], a[0][1], a[0][2], a[0][3], b0, b1);
                mma_tf32(acc[1][nt], a[1][0], a[1][1], a[1][2], a[1][3], b0, b1);
            }
        }
        __syncthreads();
    }

    // Epilogue: bias + rsqrt(deg_s), convert to fp16, store half2.
    float2 bv[8];
#pragma unroll
    for (int nt = 0; nt < 8; nt++) {
        const int n = wn * 64 + nt * 8 + tig * 2;
        bv[nt].x = __ldg(&bias[n]);
        bv[nt].y = __ldg(&bias[n + 1]);
    }
#pragma unroll
    for (int mt = 0; mt < 2; mt++) {
        const int rbase = row0 + wm * 32 + mt * 16;
        const int r0 = rbase + gid;
        const int r1 = rbase + gid + 8;
        const float s0 = (r0 < N_NODES) ? rsqrtf(fmaxf((float)g_deg_s[r0], 1.0f)) : 0.f;
        const float s1 = (r1 < N_NODES) ? rsqrtf(fmaxf((float)g_deg_s[r1], 1.0f)) : 0.f;
#pragma unroll
        for (int nt = 0; nt < 8; nt++) {
            const int n = wn * 64 + nt * 8 + tig * 2;
            if (r0 < N_NODES) {
                const __half2 o = __floats2half2_rn((acc[mt][nt].x + bv[nt].x) * s0,
                                                    (acc[mt][nt].y + bv[nt].y) * s0);
                *reinterpret_cast<__half2*>(&g_h[(size_t)r0 * D + n]) = o;
            }
            if (r1 < N_NODES) {
                const __half2 o = __floats2half2_rn((acc[mt][nt].z + bv[nt].x) * s1,
                                                    (acc[mt][nt].w + bv[nt].y) * s1);
                *reinterpret_cast<__half2*>(&g_h[(size_t)r1 * D + n]) = o;
            }
        }
    }
}

// ---------------------------------------------------------------------------
// Gather-aggregate over fp16 h, fp32 accumulation. One warp per node,
// lane handles 4 features (uint2 = 4 halfs = 8B; 32 lanes = 256B/row).
// ---------------------------------------------------------------------------
__device__ __forceinline__ void acc_row(float4& acc, const uint2 raw)
{
    const __half2 h0 = *reinterpret_cast<const __half2*>(&raw.x);
    const __half2 h1 = *reinterpret_cast<const __half2*>(&raw.y);
    const float2 f0 = __half22float2(h0);
    const float2 f1 = __half22float2(h1);
    acc.x += f0.x; acc.y += f0.y; acc.z += f1.x; acc.w += f1.y;
}

__global__ __launch_bounds__(256)
void gather_kernel(float* __restrict__ out)
{
    const int node = (blockIdx.x * blockDim.x + threadIdx.x) >> 5;
    const int lane = threadIdx.x & 31;
    if (node >= N_NODES) return;

    const int deg = g_deg_r[node];
    const int end = g_off[node];        // after fill, g_off holds row END
    const int beg = end - deg;

    float4 acc = make_float4(0.f, 0.f, 0.f, 0.f);
    const int fo = lane * 4;            // half index within row

    int j = beg;
    for (; j + 4 <= end; j += 4) {
        const int s0 = g_csr[j + 0];
        const int s1 = g_csr[j + 1];
        const int s2 = g_csr[j + 2];
        const int s3 = g_csr[j + 3];
        const uint2 v0 = *reinterpret_cast<const uint2*>(&g_h[(size_t)s0 * D + fo]);
        const uint2 v1 = *reinterpret_cast<const uint2*>(&g_h[(size_t)s1 * D + fo]);
        const uint2 v2 = *reinterpret_cast<const uint2*>(&g_h[(size_t)s2 * D + fo]);
        const uint2 v3 = *reinterpret_cast<const uint2*>(&g_h[(size_t)s3 * D + fo]);
        acc_row(acc, v0);
        acc_row(acc, v1);
        acc_row(acc, v2);
        acc_row(acc, v3);
    }
    for (; j < end; j++) {
        const int ss = g_csr[j];
        const uint2 v = *reinterpret_cast<const uint2*>(&g_h[(size_t)ss * D + fo]);
        acc_row(acc, v);
    }

    const float sc = rsqrtf(fmaxf((float)deg, 1.0f));
    acc.x *= sc; acc.y *= sc; acc.z *= sc; acc.w *= sc;
    *reinterpret_cast<float4*>(&out[(size_t)node * D + fo]) = acc;
}

// ---------------------------------------------------------------------------
extern "C" void kernel_launch(void* const* d_in, const int* in_sizes, int n_in,
                              void* d_out, int out_size)
{
    const float* x       = (const float*)d_in[0];
    const int*   senders = (const int*)d_in[1];
    const int*   recvs   = (const int*)d_in[2];
    const float* weight  = (const float*)d_in[4];
    const float* bias    = (const float*)d_in[5];
    float* out = (float*)d_out;

    zero_kernel<<<256, 256>>>();
    degree_kernel<<<(N_EDGES + 255) / 256, 256>>>(senders, recvs);

    scan_part_kernel<<<NUM_SCAN_BLOCKS, SCAN_B>>>();
    scan_add_kernel<<<(N_NODES + 255) / 256, 256>>>();

    fill_kernel<<<(N_EDGES + 255) / 256, 256>>>(senders, recvs);

    gemm_tc_kernel<<<(N_NODES + GBM - 1) / GBM, 256>>>(x, weight, bias);

    gather_kernel<<<(N_NODES * 32 + 255) / 256, 256>>>(out);
}